// round 2
// baseline (speedup 1.0000x reference)
#include <cuda_runtime.h>
#include <cuda_bf16.h>
#include <cstdint>
#include <math.h>

#define BROWS 32768
#define DDIM  512
#define FDIM  512

#define BM 128
#define BN 128
#define BK 32
#define NKC (DDIM / BK)     // 16 k-chunks
#define STAGES 3
#define GTHREADS 512        // 16 warps, 4x4 grid, 32x32 warp tile

// ---- scratch: pre-split bf16 hi/lo copies of x and W ----
__device__ __nv_bfloat16 g_x_hi[BROWS * DDIM];
__device__ __nv_bfloat16 g_x_lo[BROWS * DDIM];
__device__ __nv_bfloat16 g_w_hi[FDIM * DDIM];
__device__ __nv_bfloat16 g_w_lo[FDIM * DDIM];

// ---- SMEM layout (bytes, dynamic) ----
// [0,512)    a[] 128 floats   [512,1024) b[] 128 floats
// stages at 1024, 32 KB each: A_hi(8K) A_lo(8K) B_hi(8K) B_lo(8K)
#define SM_STAGE0   1024
#define STAGE_BYTES 32768
#define T_AHI 0
#define T_ALO 8192
#define T_BHI 16384
#define T_BLO 24576
#define SMEM_TOTAL (SM_STAGE0 + STAGES * STAGE_BYTES)   // 99328 B

__device__ __forceinline__ uint32_t s2u(const void* p) {
    uint32_t a;
    asm("{ .reg .u64 t; cvta.to.shared.u64 t, %1; cvt.u32.u64 %0, t; }" : "=r"(a) : "l"(p));
    return a;
}

// 64B rows (32 bf16), XOR swizzle: conflict-free for ldmatrix 8-row phases.
__device__ __forceinline__ uint32_t swz(int row, int c16) {
    return (uint32_t)(row * 64 + ((c16 ^ ((row >> 1) & 3)) << 4));
}

__device__ __forceinline__ void cp_async16(uint32_t saddr, const void* gptr) {
    asm volatile("cp.async.cg.shared.global [%0], [%1], 16;" :: "r"(saddr), "l"(gptr));
}
#define CP_COMMIT() asm volatile("cp.async.commit_group;" ::: "memory")
#define CP_WAIT1()  asm volatile("cp.async.wait_group 1;" ::: "memory")

__device__ __forceinline__ void ldsm4(uint32_t addr, uint32_t* r) {
    asm volatile("ldmatrix.sync.aligned.m8n8.x4.shared.b16 {%0,%1,%2,%3}, [%4];"
                 : "=r"(r[0]), "=r"(r[1]), "=r"(r[2]), "=r"(r[3]) : "r"(addr));
}

__device__ __forceinline__ void mma_bf16(float* c, const uint32_t* a, const uint32_t* b) {
    asm volatile(
        "mma.sync.aligned.m16n8k16.row.col.f32.bf16.bf16.f32 "
        "{%0,%1,%2,%3}, {%4,%5,%6,%7}, {%8,%9}, {%0,%1,%2,%3};"
        : "+f"(c[0]), "+f"(c[1]), "+f"(c[2]), "+f"(c[3])
        : "r"(a[0]), "r"(a[1]), "r"(a[2]), "r"(a[3]), "r"(b[0]), "r"(b[1]));
}

// ---------------- fp32 -> bf16 hi/lo split ----------------
__global__ void __launch_bounds__(256) convert_kernel(const float* __restrict__ src,
                                                      __nv_bfloat16* __restrict__ hi,
                                                      __nv_bfloat16* __restrict__ lo,
                                                      int n4) {
    int i = blockIdx.x * blockDim.x + threadIdx.x;
    int stride = gridDim.x * blockDim.x;
    for (; i < n4; i += stride) {
        float4 v = reinterpret_cast<const float4*>(src)[i];
        __nv_bfloat16 h0 = __float2bfloat16_rn(v.x), h1 = __float2bfloat16_rn(v.y);
        __nv_bfloat16 h2 = __float2bfloat16_rn(v.z), h3 = __float2bfloat16_rn(v.w);
        __nv_bfloat16 l0 = __float2bfloat16_rn(v.x - __bfloat162float(h0));
        __nv_bfloat16 l1 = __float2bfloat16_rn(v.y - __bfloat162float(h1));
        __nv_bfloat16 l2 = __float2bfloat16_rn(v.z - __bfloat162float(h2));
        __nv_bfloat16 l3 = __float2bfloat16_rn(v.w - __bfloat162float(h3));
        uint2 hp, lp;
        hp.x = ((uint32_t)__bfloat16_as_ushort(h1) << 16) | __bfloat16_as_ushort(h0);
        hp.y = ((uint32_t)__bfloat16_as_ushort(h3) << 16) | __bfloat16_as_ushort(h2);
        lp.x = ((uint32_t)__bfloat16_as_ushort(l1) << 16) | __bfloat16_as_ushort(l0);
        lp.y = ((uint32_t)__bfloat16_as_ushort(l3) << 16) | __bfloat16_as_ushort(l2);
        reinterpret_cast<uint2*>(hi)[i] = hp;
        reinterpret_cast<uint2*>(lo)[i] = lp;
    }
}

// ---------------- GEMM + tanh epilogue ----------------
__device__ __forceinline__ void load_stage(uint32_t stage_base, int m0, int n0, int kc, int tid) {
    int r = tid >> 2;          // 0..127
    int c = tid & 3;           // 16B chunk within 64B row
    uint32_t soff = swz(r, c);
    size_t gx = (size_t)(m0 + r) * DDIM + (size_t)kc * BK + c * 8;
    size_t gw = (size_t)(n0 + r) * DDIM + (size_t)kc * BK + c * 8;
    cp_async16(stage_base + T_AHI + soff, g_x_hi + gx);
    cp_async16(stage_base + T_ALO + soff, g_x_lo + gx);
    cp_async16(stage_base + T_BHI + soff, g_w_hi + gw);
    cp_async16(stage_base + T_BLO + soff, g_w_lo + gw);
}

__global__ void __launch_bounds__(GTHREADS, 1)
rank_activation_gemm(const float* __restrict__ av, const float* __restrict__ bv,
                     float* __restrict__ out) {
    extern __shared__ char smem[];
    uint32_t sm = s2u(smem);
    int tid = threadIdx.x;
    int wid = tid >> 5;
    int l = tid & 31;
    int wm = wid >> 2;   // 0..3, 32 rows each
    int wn = wid & 3;    // 0..3, 32 cols each

    // N-major inner order: 4 consecutive CTAs share the same x (A) tile in L2
    int m0 = (int)(blockIdx.x >> 2) * BM;
    int n0 = (int)(blockIdx.x & 3) * BN;

    if (tid < 128) {
        ((float*)smem)[tid]       = av[n0 + tid];
        ((float*)smem)[128 + tid] = bv[n0 + tid];
    }

    // per-lane ldmatrix offsets (within a tile)
    int g = l >> 3;
    uint32_t a_sw[2][2], b_sw[2][2];
#pragma unroll
    for (int mt = 0; mt < 2; mt++) {
        int row = wm * 32 + mt * 16 + ((g & 1) << 3) + (l & 7);
#pragma unroll
        for (int s = 0; s < 2; s++) a_sw[mt][s] = swz(row, s * 2 + (g >> 1));
    }
#pragma unroll
    for (int t = 0; t < 2; t++) {
        int row = wn * 32 + t * 16 + ((g >> 1) << 3) + (l & 7);
#pragma unroll
        for (int s = 0; s < 2; s++) b_sw[t][s] = swz(row, s * 2 + (g & 1));
    }

    float acc[2][4][4];
#pragma unroll
    for (int i = 0; i < 2; i++)
#pragma unroll
        for (int j = 0; j < 4; j++)
#pragma unroll
            for (int k = 0; k < 4; k++) acc[i][j][k] = 0.0f;

    // prologue: stages 0 and 1
    load_stage(sm + SM_STAGE0, m0, n0, 0, tid);
    CP_COMMIT();
    load_stage(sm + SM_STAGE0 + STAGE_BYTES, m0, n0, 1, tid);
    CP_COMMIT();

    for (int kc = 0; kc < NKC; kc++) {
        CP_WAIT1();
        __syncthreads();

        if (kc + 2 < NKC)
            load_stage(sm + SM_STAGE0 + ((kc + 2) % STAGES) * STAGE_BYTES, m0, n0, kc + 2, tid);
        CP_COMMIT();   // keep group accounting uniform

        uint32_t st = sm + SM_STAGE0 + (kc % STAGES) * STAGE_BYTES;
#pragma unroll
        for (int s = 0; s < 2; s++) {   // two k16 steps per 32-chunk
            uint32_t Ahi[2][4], Alo[2][4], Bhi[2][4], Blo[2][4];
#pragma unroll
            for (int mt = 0; mt < 2; mt++) {
                ldsm4(st + T_AHI + a_sw[mt][s], Ahi[mt]);
                ldsm4(st + T_ALO + a_sw[mt][s], Alo[mt]);
            }
#pragma unroll
            for (int t = 0; t < 2; t++) {
                ldsm4(st + T_BHI + b_sw[t][s], Bhi[t]);
                ldsm4(st + T_BLO + b_sw[t][s], Blo[t]);
            }
#pragma unroll
            for (int mt = 0; mt < 2; mt++) {
#pragma unroll
                for (int nt = 0; nt < 4; nt++) {
                    const uint32_t* bh = &Bhi[nt >> 1][(nt & 1) * 2];
                    const uint32_t* bl = &Blo[nt >> 1][(nt & 1) * 2];
                    mma_bf16(acc[mt][nt], Ahi[mt], bh);   // hi*hi
                    mma_bf16(acc[mt][nt], Alo[mt], bh);   // lo*hi
                    mma_bf16(acc[mt][nt], Ahi[mt], bl);   // hi*lo
                }
            }
        }
    }

    // epilogue: out = tanh(a*z + b)
    const float* sA = (const float*)smem;
    const float* sB = (const float*)smem + 128;
#pragma unroll
    for (int mt = 0; mt < 2; mt++) {
        int row = m0 + wm * 32 + mt * 16 + (l >> 2);
#pragma unroll
        for (int nt = 0; nt < 4; nt++) {
            int cl = wn * 32 + nt * 8 + 2 * (l & 3);
            float a0 = sA[cl], a1 = sA[cl + 1];
            float b0 = sB[cl], b1 = sB[cl + 1];
            float2 v0, v1;
            v0.x = tanhf(fmaf(a0, acc[mt][nt][0], b0));
            v0.y = tanhf(fmaf(a1, acc[mt][nt][1], b1));
            v1.x = tanhf(fmaf(a0, acc[mt][nt][2], b0));
            v1.y = tanhf(fmaf(a1, acc[mt][nt][3], b1));
            *reinterpret_cast<float2*>(out + (size_t)row * FDIM + n0 + cl) = v0;
            *reinterpret_cast<float2*>(out + (size_t)(row + 8) * FDIM + n0 + cl) = v1;
        }
    }
}

extern "C" void kernel_launch(void* const* d_in, const int* in_sizes, int n_in,
                              void* d_out, int out_size) {
    const float* x = (const float*)d_in[0];
    const float* W = (const float*)d_in[1];
    const float* a = (const float*)d_in[2];
    const float* b = (const float*)d_in[3];
    float* out = (float*)d_out;

    __nv_bfloat16 *xh, *xl, *wh, *wl;
    cudaGetSymbolAddress((void**)&xh, g_x_hi);
    cudaGetSymbolAddress((void**)&xl, g_x_lo);
    cudaGetSymbolAddress((void**)&wh, g_w_hi);
    cudaGetSymbolAddress((void**)&wl, g_w_lo);

    convert_kernel<<<2048, 256>>>(x, xh, xl, BROWS * DDIM / 4);
    convert_kernel<<<256, 256>>>(W, wh, wl, FDIM * DDIM / 4);

    static bool attr_set = false;
    if (!attr_set) {
        cudaFuncSetAttribute(rank_activation_gemm,
                             cudaFuncAttributeMaxDynamicSharedMemorySize, SMEM_TOTAL);
        attr_set = true;
    }
    dim3 grid((BROWS / BM) * (FDIM / BN));   // 1024
    rank_activation_gemm<<<grid, GTHREADS, SMEM_TOTAL>>>(a, b, out);
}

// round 3
// speedup vs baseline: 1.1179x; 1.1179x over previous
#include <cuda_runtime.h>
#include <cuda_bf16.h>
#include <cstdint>
#include <math.h>

#define BROWS 32768
#define DDIM  512
#define FDIM  512

#define BM 128
#define BN 64
#define BK 32
#define NKC (DDIM / BK)     // 16 k-chunks
#define STAGES 3
#define GTHREADS 256        // 8 warps, 4x2 grid, 32x32 warp tiles

// ---- scratch: pre-split bf16 hi/lo copies of x and W ----
__device__ __nv_bfloat16 g_x_hi[BROWS * DDIM];
__device__ __nv_bfloat16 g_x_lo[BROWS * DDIM];
__device__ __nv_bfloat16 g_w_hi[FDIM * DDIM];
__device__ __nv_bfloat16 g_w_lo[FDIM * DDIM];

// ---- SMEM layout (bytes, dynamic) ----
// [0,256) a[] 64 floats, [256,512) b[] 64 floats
// stages at 1024, 24 KB each: A_hi(8K) A_lo(8K) B_hi(4K) B_lo(4K)
#define SM_STAGE0   1024
#define STAGE_BYTES 24576
#define T_AHI 0
#define T_ALO 8192
#define T_BHI 16384
#define T_BLO 20480
#define SMEM_TOTAL (SM_STAGE0 + STAGES * STAGE_BYTES)   // 74752 B -> 2 CTAs/SM

__device__ __forceinline__ uint32_t s2u(const void* p) {
    uint32_t a;
    asm("{ .reg .u64 t; cvta.to.shared.u64 t, %1; cvt.u32.u64 %0, t; }" : "=r"(a) : "l"(p));
    return a;
}

// 64B rows (32 bf16), XOR swizzle: conflict-free for ldmatrix 8-row phases.
__device__ __forceinline__ uint32_t swz(int row, int c16) {
    return (uint32_t)(row * 64 + ((c16 ^ ((row >> 1) & 3)) << 4));
}

__device__ __forceinline__ void cp_async16(uint32_t saddr, const void* gptr) {
    asm volatile("cp.async.cg.shared.global [%0], [%1], 16;" :: "r"(saddr), "l"(gptr));
}
#define CP_COMMIT() asm volatile("cp.async.commit_group;" ::: "memory")
#define CP_WAIT1()  asm volatile("cp.async.wait_group 1;" ::: "memory")

__device__ __forceinline__ void ldsm4(uint32_t addr, uint32_t* r) {
    asm volatile("ldmatrix.sync.aligned.m8n8.x4.shared.b16 {%0,%1,%2,%3}, [%4];"
                 : "=r"(r[0]), "=r"(r[1]), "=r"(r[2]), "=r"(r[3]) : "r"(addr));
}

__device__ __forceinline__ void mma_bf16(float* c, const uint32_t* a, const uint32_t* b) {
    asm volatile(
        "mma.sync.aligned.m16n8k16.row.col.f32.bf16.bf16.f32 "
        "{%0,%1,%2,%3}, {%4,%5,%6,%7}, {%8,%9}, {%0,%1,%2,%3};"
        : "+f"(c[0]), "+f"(c[1]), "+f"(c[2]), "+f"(c[3])
        : "r"(a[0]), "r"(a[1]), "r"(a[2]), "r"(a[3]), "r"(b[0]), "r"(b[1]));
}

// ---------------- fp32 -> bf16 hi/lo split (x and W in one launch) ----------------
// unit of work = 8 consecutive floats -> one 16B hi store + one 16B lo store
#define XN8 (BROWS * DDIM / 8)
#define WN8 (FDIM * DDIM / 8)
#define CONV_BLOCKS 2080   // 2080*256*4 == XN8+WN8 exactly

__device__ __forceinline__ void split8(const float* __restrict__ src, size_t i8,
                                       __nv_bfloat16* __restrict__ hi,
                                       __nv_bfloat16* __restrict__ lo) {
    float4 v0 = reinterpret_cast<const float4*>(src)[i8 * 2];
    float4 v1 = reinterpret_cast<const float4*>(src)[i8 * 2 + 1];
    float f[8] = {v0.x, v0.y, v0.z, v0.w, v1.x, v1.y, v1.z, v1.w};
    uint32_t hp[4], lp[4];
#pragma unroll
    for (int j = 0; j < 4; j++) {
        __nv_bfloat16 h0 = __float2bfloat16_rn(f[2 * j]);
        __nv_bfloat16 h1 = __float2bfloat16_rn(f[2 * j + 1]);
        __nv_bfloat16 l0 = __float2bfloat16_rn(f[2 * j] - __bfloat162float(h0));
        __nv_bfloat16 l1 = __float2bfloat16_rn(f[2 * j + 1] - __bfloat162float(h1));
        hp[j] = ((uint32_t)__bfloat16_as_ushort(h1) << 16) | __bfloat16_as_ushort(h0);
        lp[j] = ((uint32_t)__bfloat16_as_ushort(l1) << 16) | __bfloat16_as_ushort(l0);
    }
    reinterpret_cast<uint4*>(hi)[i8] = make_uint4(hp[0], hp[1], hp[2], hp[3]);
    reinterpret_cast<uint4*>(lo)[i8] = make_uint4(lp[0], lp[1], lp[2], lp[3]);
}

__global__ void __launch_bounds__(256) convert_all(const float* __restrict__ x,
                                                   const float* __restrict__ W) {
    size_t i = (size_t)blockIdx.x * blockDim.x + threadIdx.x;
    size_t stride = (size_t)gridDim.x * blockDim.x;
    for (; i < XN8 + WN8; i += stride) {
        if (i < XN8) split8(x, i, g_x_hi, g_x_lo);
        else         split8(W, i - XN8, g_w_hi, g_w_lo);
    }
}

// ---------------- GEMM + tanh epilogue ----------------
__device__ __forceinline__ void load_stage(uint32_t stage_base, int m0, int n0, int kc, int tid) {
    // A: 128 rows x 4 c16-chunks per array -> 512 chunks, 2 per thread
#pragma unroll
    for (int q = tid; q < 512; q += 256) {
        int r = q >> 2, c = q & 3;
        uint32_t soff = swz(r, c);
        size_t gx = (size_t)(m0 + r) * DDIM + (size_t)kc * BK + c * 8;
        cp_async16(stage_base + T_AHI + soff, g_x_hi + gx);
        cp_async16(stage_base + T_ALO + soff, g_x_lo + gx);
    }
    // B: 64 rows x 4 chunks per array -> 256 chunks, 1 per thread
    {
        int r = tid >> 2, c = tid & 3;
        uint32_t soff = swz(r, c);
        size_t gw = (size_t)(n0 + r) * DDIM + (size_t)kc * BK + c * 8;
        cp_async16(stage_base + T_BHI + soff, g_w_hi + gw);
        cp_async16(stage_base + T_BLO + soff, g_w_lo + gw);
    }
}

__global__ void __launch_bounds__(GTHREADS, 2)
rank_activation_gemm(const float* __restrict__ av, const float* __restrict__ bv,
                     float* __restrict__ out) {
    extern __shared__ char smem[];
    uint32_t sm = s2u(smem);
    int tid = threadIdx.x;
    int wid = tid >> 5;
    int l = tid & 31;
    int wm = wid >> 1;   // 0..3, 32 rows each
    int wn = wid & 1;    // 0..1, 32 cols each

    // N-major inner order: 8 consecutive CTAs share the same x (A) tile in L2
    int m0 = (int)(blockIdx.x >> 3) * BM;
    int n0 = (int)(blockIdx.x & 7) * BN;

    if (tid < 64) {
        ((float*)smem)[tid]      = av[n0 + tid];
        ((float*)smem)[64 + tid] = bv[n0 + tid];
    }

    // per-lane ldmatrix offsets (within a tile)
    int g = l >> 3;
    uint32_t a_sw[2][2], b_sw[2][2];
#pragma unroll
    for (int mt = 0; mt < 2; mt++) {
        int row = wm * 32 + mt * 16 + ((g & 1) << 3) + (l & 7);
#pragma unroll
        for (int s = 0; s < 2; s++) a_sw[mt][s] = swz(row, s * 2 + (g >> 1));
    }
#pragma unroll
    for (int t = 0; t < 2; t++) {
        int row = wn * 32 + t * 16 + ((g >> 1) << 3) + (l & 7);
#pragma unroll
        for (int s = 0; s < 2; s++) b_sw[t][s] = swz(row, s * 2 + (g & 1));
    }

    float acc[2][4][4];
#pragma unroll
    for (int i = 0; i < 2; i++)
#pragma unroll
        for (int j = 0; j < 4; j++)
#pragma unroll
            for (int k = 0; k < 4; k++) acc[i][j][k] = 0.0f;

    // prologue: stages 0 and 1
    load_stage(sm + SM_STAGE0, m0, n0, 0, tid);
    CP_COMMIT();
    load_stage(sm + SM_STAGE0 + STAGE_BYTES, m0, n0, 1, tid);
    CP_COMMIT();

    for (int kc = 0; kc < NKC; kc++) {
        CP_WAIT1();
        __syncthreads();

        if (kc + 2 < NKC)
            load_stage(sm + SM_STAGE0 + ((kc + 2) % STAGES) * STAGE_BYTES, m0, n0, kc + 2, tid);
        CP_COMMIT();   // uniform group accounting

        uint32_t st = sm + SM_STAGE0 + (kc % STAGES) * STAGE_BYTES;
#pragma unroll
        for (int s = 0; s < 2; s++) {   // two k16 steps per 32-chunk
            uint32_t Ahi[2][4], Alo[2][4], Bhi[2][4], Blo[2][4];
#pragma unroll
            for (int mt = 0; mt < 2; mt++) {
                ldsm4(st + T_AHI + a_sw[mt][s], Ahi[mt]);
                ldsm4(st + T_ALO + a_sw[mt][s], Alo[mt]);
            }
#pragma unroll
            for (int t = 0; t < 2; t++) {
                ldsm4(st + T_BHI + b_sw[t][s], Bhi[t]);
                ldsm4(st + T_BLO + b_sw[t][s], Blo[t]);
            }
#pragma unroll
            for (int mt = 0; mt < 2; mt++) {
#pragma unroll
                for (int nt = 0; nt < 4; nt++) {
                    const uint32_t* bh = &Bhi[nt >> 1][(nt & 1) * 2];
                    const uint32_t* bl = &Blo[nt >> 1][(nt & 1) * 2];
                    mma_bf16(acc[mt][nt], Ahi[mt], bh);   // hi*hi
                    mma_bf16(acc[mt][nt], Alo[mt], bh);   // lo*hi
                    mma_bf16(acc[mt][nt], Ahi[mt], bl);   // hi*lo
                }
            }
        }
    }

    // epilogue: out = tanh(a*z + b)
    const float* sA = (const float*)smem;
    const float* sB = (const float*)smem + 64;
#pragma unroll
    for (int mt = 0; mt < 2; mt++) {
        int row = m0 + wm * 32 + mt * 16 + (l >> 2);
#pragma unroll
        for (int nt = 0; nt < 4; nt++) {
            int cl = wn * 32 + nt * 8 + 2 * (l & 3);
            float a0 = sA[cl], a1 = sA[cl + 1];
            float b0 = sB[cl], b1 = sB[cl + 1];
            float2 v0, v1;
            v0.x = tanhf(fmaf(a0, acc[mt][nt][0], b0));
            v0.y = tanhf(fmaf(a1, acc[mt][nt][1], b1));
            v1.x = tanhf(fmaf(a0, acc[mt][nt][2], b0));
            v1.y = tanhf(fmaf(a1, acc[mt][nt][3], b1));
            *reinterpret_cast<float2*>(out + (size_t)row * FDIM + n0 + cl) = v0;
            *reinterpret_cast<float2*>(out + (size_t)(row + 8) * FDIM + n0 + cl) = v1;
        }
    }
}

extern "C" void kernel_launch(void* const* d_in, const int* in_sizes, int n_in,
                              void* d_out, int out_size) {
    const float* x = (const float*)d_in[0];
    const float* W = (const float*)d_in[1];
    const float* a = (const float*)d_in[2];
    const float* b = (const float*)d_in[3];
    float* out = (float*)d_out;

    convert_all<<<CONV_BLOCKS, 256>>>(x, W);

    cudaFuncSetAttribute(rank_activation_gemm,
                         cudaFuncAttributeMaxDynamicSharedMemorySize, SMEM_TOTAL);
    dim3 grid((BROWS / BM) * (FDIM / BN));   // 256 * 8 = 2048
    rank_activation_gemm<<<grid, GTHREADS, SMEM_TOTAL>>>(a, b, out);
}

// round 4
// speedup vs baseline: 1.4698x; 1.3149x over previous
#include <cuda_runtime.h>
#include <cuda_fp16.h>
#include <cstdint>
#include <math.h>

#define BROWS 32768
#define DDIM  512
#define FDIM  512

#define BM 128
#define BN 128
#define BK 32
#define NKC (DDIM / BK)     // 16 k-chunks
#define STAGES 4
#define GTHREADS 256        // 8 warps, 2x4 grid, 64x32 warp tiles

// ---- scratch: x split into fp16 hi/lo, W as single fp16 ----
__device__ __half g_x_hi[BROWS * DDIM];
__device__ __half g_x_lo[BROWS * DDIM];
__device__ __half g_w[FDIM * DDIM];

// ---- SMEM layout (bytes, dynamic) ----
// [0,512) a[] 128 floats, [512,1024) b[] 128 floats
// stages at 1024, 24 KB each: A_hi(8K) A_lo(8K) B(8K)
#define SM_STAGE0   1024
#define STAGE_BYTES 24576
#define T_AHI 0
#define T_ALO 8192
#define T_B   16384
#define SMEM_TOTAL (SM_STAGE0 + STAGES * STAGE_BYTES)   // 99328 B -> 2 CTAs/SM

__device__ __forceinline__ uint32_t s2u(const void* p) {
    uint32_t a;
    asm("{ .reg .u64 t; cvta.to.shared.u64 t, %1; cvt.u32.u64 %0, t; }" : "=r"(a) : "l"(p));
    return a;
}

// 64B rows (32 fp16), XOR swizzle: conflict-free for ldmatrix 8-row phases.
__device__ __forceinline__ uint32_t swz(int row, int c16) {
    return (uint32_t)(row * 64 + ((c16 ^ ((row >> 1) & 3)) << 4));
}

__device__ __forceinline__ void cp_async16(uint32_t saddr, const void* gptr) {
    asm volatile("cp.async.cg.shared.global [%0], [%1], 16;" :: "r"(saddr), "l"(gptr));
}
#define CP_COMMIT() asm volatile("cp.async.commit_group;" ::: "memory")
#define CP_WAIT2()  asm volatile("cp.async.wait_group 2;" ::: "memory")

__device__ __forceinline__ void ldsm4(uint32_t addr, uint32_t* r) {
    asm volatile("ldmatrix.sync.aligned.m8n8.x4.shared.b16 {%0,%1,%2,%3}, [%4];"
                 : "=r"(r[0]), "=r"(r[1]), "=r"(r[2]), "=r"(r[3]) : "r"(addr));
}

__device__ __forceinline__ void mma_f16(float* c, const uint32_t* a, const uint32_t* b) {
    asm volatile(
        "mma.sync.aligned.m16n8k16.row.col.f32.f16.f16.f32 "
        "{%0,%1,%2,%3}, {%4,%5,%6,%7}, {%8,%9}, {%0,%1,%2,%3};"
        : "+f"(c[0]), "+f"(c[1]), "+f"(c[2]), "+f"(c[3])
        : "r"(a[0]), "r"(a[1]), "r"(a[2]), "r"(a[3]), "r"(b[0]), "r"(b[1]));
}

// ---------------- fp32 -> fp16 split (x hi/lo) + W fp16, one launch ----------------
#define XN8 (BROWS * DDIM / 8)
#define WN8 (FDIM * DDIM / 8)
#define CONV_BLOCKS 2080   // 2080*256*4 == XN8+WN8 exactly

__device__ __forceinline__ void split8_x(const float* __restrict__ src, size_t i8) {
    float4 v0 = reinterpret_cast<const float4*>(src)[i8 * 2];
    float4 v1 = reinterpret_cast<const float4*>(src)[i8 * 2 + 1];
    float f[8] = {v0.x, v0.y, v0.z, v0.w, v1.x, v1.y, v1.z, v1.w};
    uint32_t hp[4], lp[4];
#pragma unroll
    for (int j = 0; j < 4; j++) {
        __half h0 = __float2half_rn(f[2 * j]);
        __half h1 = __float2half_rn(f[2 * j + 1]);
        __half l0 = __float2half_rn(f[2 * j] - __half2float(h0));
        __half l1 = __float2half_rn(f[2 * j + 1] - __half2float(h1));
        hp[j] = ((uint32_t)__half_as_ushort(h1) << 16) | __half_as_ushort(h0);
        lp[j] = ((uint32_t)__half_as_ushort(l1) << 16) | __half_as_ushort(l0);
    }
    reinterpret_cast<uint4*>(g_x_hi)[i8] = make_uint4(hp[0], hp[1], hp[2], hp[3]);
    reinterpret_cast<uint4*>(g_x_lo)[i8] = make_uint4(lp[0], lp[1], lp[2], lp[3]);
}

__device__ __forceinline__ void conv8_w(const float* __restrict__ src, size_t i8) {
    float4 v0 = reinterpret_cast<const float4*>(src)[i8 * 2];
    float4 v1 = reinterpret_cast<const float4*>(src)[i8 * 2 + 1];
    float f[8] = {v0.x, v0.y, v0.z, v0.w, v1.x, v1.y, v1.z, v1.w};
    uint32_t hp[4];
#pragma unroll
    for (int j = 0; j < 4; j++) {
        __half h0 = __float2half_rn(f[2 * j]);
        __half h1 = __float2half_rn(f[2 * j + 1]);
        hp[j] = ((uint32_t)__half_as_ushort(h1) << 16) | __half_as_ushort(h0);
    }
    reinterpret_cast<uint4*>(g_w)[i8] = make_uint4(hp[0], hp[1], hp[2], hp[3]);
}

__global__ void __launch_bounds__(256) convert_all(const float* __restrict__ x,
                                                   const float* __restrict__ W) {
    size_t i = (size_t)blockIdx.x * blockDim.x + threadIdx.x;
    size_t stride = (size_t)gridDim.x * blockDim.x;
    for (; i < XN8 + WN8; i += stride) {
        if (i < XN8) split8_x(x, i);
        else         conv8_w(W, i - XN8);
    }
}

// ---------------- GEMM + tanh epilogue ----------------
__device__ __forceinline__ void load_stage(uint32_t stage_base, int m0, int n0, int kc, int tid) {
    // A and B both 128 rows x 4 c16-chunks -> 512 chunks each, 2 per thread
#pragma unroll
    for (int q = tid; q < 512; q += 256) {
        int r = q >> 2, c = q & 3;
        uint32_t soff = swz(r, c);
        size_t gx = (size_t)(m0 + r) * DDIM + (size_t)kc * BK + c * 8;
        size_t gw = (size_t)(n0 + r) * DDIM + (size_t)kc * BK + c * 8;
        cp_async16(stage_base + T_AHI + soff, g_x_hi + gx);
        cp_async16(stage_base + T_ALO + soff, g_x_lo + gx);
        cp_async16(stage_base + T_B + soff, g_w + gw);
    }
}

__global__ void __launch_bounds__(GTHREADS, 2)
rank_activation_gemm(const float* __restrict__ av, const float* __restrict__ bv,
                     float* __restrict__ out) {
    extern __shared__ char smem[];
    uint32_t sm = s2u(smem);
    int tid = threadIdx.x;
    int wid = tid >> 5;
    int l = tid & 31;
    int wm = wid >> 2;   // 0..1, 64 rows each
    int wn = wid & 3;    // 0..3, 32 cols each

    // N-major inner order: 4 consecutive CTAs share the same x (A) tile in L2
    int m0 = (int)(blockIdx.x >> 2) * BM;
    int n0 = (int)(blockIdx.x & 3) * BN;

    if (tid < 128) {
        ((float*)smem)[tid]       = av[n0 + tid];
        ((float*)smem)[128 + tid] = bv[n0 + tid];
    }

    // per-lane ldmatrix offsets (within a tile)
    int g = l >> 3;
    uint32_t a_sw[4][2], b_sw[2][2];
#pragma unroll
    for (int mt = 0; mt < 4; mt++) {
        int row = wm * 64 + mt * 16 + ((g & 1) << 3) + (l & 7);
#pragma unroll
        for (int s = 0; s < 2; s++) a_sw[mt][s] = swz(row, s * 2 + (g >> 1));
    }
#pragma unroll
    for (int t = 0; t < 2; t++) {
        int row = wn * 32 + t * 16 + ((g >> 1) << 3) + (l & 7);
#pragma unroll
        for (int s = 0; s < 2; s++) b_sw[t][s] = swz(row, s * 2 + (g & 1));
    }

    float acc[4][4][4];
#pragma unroll
    for (int i = 0; i < 4; i++)
#pragma unroll
        for (int j = 0; j < 4; j++)
#pragma unroll
            for (int k = 0; k < 4; k++) acc[i][j][k] = 0.0f;

    // prologue: stages 0,1,2
    load_stage(sm + SM_STAGE0, m0, n0, 0, tid);
    CP_COMMIT();
    load_stage(sm + SM_STAGE0 + STAGE_BYTES, m0, n0, 1, tid);
    CP_COMMIT();
    load_stage(sm + SM_STAGE0 + 2 * STAGE_BYTES, m0, n0, 2, tid);
    CP_COMMIT();

    for (int kc = 0; kc < NKC; kc++) {
        CP_WAIT2();
        __syncthreads();

        if (kc + 3 < NKC)
            load_stage(sm + SM_STAGE0 + ((kc + 3) % STAGES) * STAGE_BYTES, m0, n0, kc + 3, tid);
        CP_COMMIT();   // uniform group accounting

        uint32_t st = sm + SM_STAGE0 + (kc % STAGES) * STAGE_BYTES;
#pragma unroll
        for (int s = 0; s < 2; s++) {   // two k16 steps per 32-chunk
            uint32_t Ahi[4][4], Alo[4][4], B[2][4];
#pragma unroll
            for (int t = 0; t < 2; t++) ldsm4(st + T_B + b_sw[t][s], B[t]);
#pragma unroll
            for (int mt = 0; mt < 4; mt++) {
                ldsm4(st + T_AHI + a_sw[mt][s], Ahi[mt]);
                ldsm4(st + T_ALO + a_sw[mt][s], Alo[mt]);
            }
#pragma unroll
            for (int mt = 0; mt < 4; mt++) {
#pragma unroll
                for (int nt = 0; nt < 4; nt++) {
                    const uint32_t* bf = &B[nt >> 1][(nt & 1) * 2];
                    mma_f16(acc[mt][nt], Ahi[mt], bf);   // x_hi * W
                    mma_f16(acc[mt][nt], Alo[mt], bf);   // x_lo * W
                }
            }
        }
    }

    // epilogue: out = tanh(a*z + b)
    const float* sA = (const float*)smem;
    const float* sB = (const float*)smem + 128;
#pragma unroll
    for (int mt = 0; mt < 4; mt++) {
        int row = m0 + wm * 64 + mt * 16 + (l >> 2);
#pragma unroll
        for (int nt = 0; nt < 4; nt++) {
            int cl = wn * 32 + nt * 8 + 2 * (l & 3);
            float a0 = sA[cl], a1 = sA[cl + 1];
            float b0 = sB[cl], b1 = sB[cl + 1];
            float2 v0, v1;
            v0.x = tanhf(fmaf(a0, acc[mt][nt][0], b0));
            v0.y = tanhf(fmaf(a1, acc[mt][nt][1], b1));
            v1.x = tanhf(fmaf(a0, acc[mt][nt][2], b0));
            v1.y = tanhf(fmaf(a1, acc[mt][nt][3], b1));
            *reinterpret_cast<float2*>(out + (size_t)row * FDIM + n0 + cl) = v0;
            *reinterpret_cast<float2*>(out + (size_t)(row + 8) * FDIM + n0 + cl) = v1;
        }
    }
}

extern "C" void kernel_launch(void* const* d_in, const int* in_sizes, int n_in,
                              void* d_out, int out_size) {
    const float* x = (const float*)d_in[0];
    const float* W = (const float*)d_in[1];
    const float* a = (const float*)d_in[2];
    const float* b = (const float*)d_in[3];
    float* out = (float*)d_out;

    convert_all<<<CONV_BLOCKS, 256>>>(x, W);

    cudaFuncSetAttribute(rank_activation_gemm,
                         cudaFuncAttributeMaxDynamicSharedMemorySize, SMEM_TOTAL);
    dim3 grid((BROWS / BM) * (FDIM / BN));   // 256 * 4 = 1024
    rank_activation_gemm<<<grid, GTHREADS, SMEM_TOTAL>>>(a, b, out);
}

// round 5
// speedup vs baseline: 2.2376x; 1.5223x over previous
#include <cuda_runtime.h>
#include <cuda_fp16.h>
#include <cstdint>
#include <math.h>

#define BROWS 32768
#define DDIM  512
#define FDIM  512

#define BM 128
#define BN 128
#define BK 32
#define NKC (DDIM / BK)     // 16 k-chunks
#define STAGES 6
#define GTHREADS 256        // 8 warps, 2x4 grid, 64x32 warp tiles

// ---- scratch: x and W as fp16 ----
__device__ __half g_x[BROWS * DDIM];
__device__ __half g_w[FDIM * DDIM];

// ---- SMEM layout (bytes, dynamic) ----
// [0,512) a[] 128 floats, [512,1024) b[] 128 floats
// stages at 1024, 16 KB each: A(8K) B(8K)
#define SM_STAGE0   1024
#define STAGE_BYTES 16384
#define T_A 0
#define T_B 8192
#define SMEM_TOTAL (SM_STAGE0 + STAGES * STAGE_BYTES)   // 99328 B -> 2 CTAs/SM

__device__ __forceinline__ uint32_t s2u(const void* p) {
    uint32_t a;
    asm("{ .reg .u64 t; cvta.to.shared.u64 t, %1; cvt.u32.u64 %0, t; }" : "=r"(a) : "l"(p));
    return a;
}

// 64B rows (32 fp16), XOR swizzle: conflict-free for ldmatrix 8-row phases.
__device__ __forceinline__ uint32_t swz(int row, int c16) {
    return (uint32_t)(row * 64 + ((c16 ^ ((row >> 1) & 3)) << 4));
}

__device__ __forceinline__ void cp_async16(uint32_t saddr, const void* gptr) {
    asm volatile("cp.async.cg.shared.global [%0], [%1], 16;" :: "r"(saddr), "l"(gptr));
}
#define CP_COMMIT() asm volatile("cp.async.commit_group;" ::: "memory")
#define CP_WAIT4()  asm volatile("cp.async.wait_group 4;" ::: "memory")

__device__ __forceinline__ void ldsm4(uint32_t addr, uint32_t* r) {
    asm volatile("ldmatrix.sync.aligned.m8n8.x4.shared.b16 {%0,%1,%2,%3}, [%4];"
                 : "=r"(r[0]), "=r"(r[1]), "=r"(r[2]), "=r"(r[3]) : "r"(addr));
}

__device__ __forceinline__ void mma_f16(float* c, const uint32_t* a, const uint32_t* b) {
    asm volatile(
        "mma.sync.aligned.m16n8k16.row.col.f32.f16.f16.f32 "
        "{%0,%1,%2,%3}, {%4,%5,%6,%7}, {%8,%9}, {%0,%1,%2,%3};"
        : "+f"(c[0]), "+f"(c[1]), "+f"(c[2]), "+f"(c[3])
        : "r"(a[0]), "r"(a[1]), "r"(a[2]), "r"(a[3]), "r"(b[0]), "r"(b[1]));
}

// ---------------- fp32 -> fp16 convert (x and W), one launch ----------------
#define XN8 (BROWS * DDIM / 8)
#define WN8 (FDIM * DDIM / 8)
#define CONV_BLOCKS 2080   // 2080*256*4 == XN8+WN8 exactly

__device__ __forceinline__ void conv8(const float* __restrict__ src, size_t i8,
                                      __half* __restrict__ dst) {
    float4 v0 = reinterpret_cast<const float4*>(src)[i8 * 2];
    float4 v1 = reinterpret_cast<const float4*>(src)[i8 * 2 + 1];
    float f[8] = {v0.x, v0.y, v0.z, v0.w, v1.x, v1.y, v1.z, v1.w};
    uint32_t hp[4];
#pragma unroll
    for (int j = 0; j < 4; j++) {
        __half h0 = __float2half_rn(f[2 * j]);
        __half h1 = __float2half_rn(f[2 * j + 1]);
        hp[j] = ((uint32_t)__half_as_ushort(h1) << 16) | __half_as_ushort(h0);
    }
    reinterpret_cast<uint4*>(dst)[i8] = make_uint4(hp[0], hp[1], hp[2], hp[3]);
}

__global__ void __launch_bounds__(256) convert_all(const float* __restrict__ x,
                                                   const float* __restrict__ W) {
    size_t i = (size_t)blockIdx.x * blockDim.x + threadIdx.x;
    size_t stride = (size_t)gridDim.x * blockDim.x;
    for (; i < XN8 + WN8; i += stride) {
        if (i < XN8) conv8(x, i, g_x);
        else         conv8(W, i - XN8, g_w);
    }
}

// ---------------- GEMM + tanh epilogue ----------------
__device__ __forceinline__ void load_stage(uint32_t stage_base, int m0, int n0, int kc, int tid) {
    // A and B both 128 rows x 4 c16-chunks -> 512 chunks each, 2 per thread each
#pragma unroll
    for (int q = tid; q < 512; q += 256) {
        int r = q >> 2, c = q & 3;
        uint32_t soff = swz(r, c);
        size_t gx = (size_t)(m0 + r) * DDIM + (size_t)kc * BK + c * 8;
        size_t gw = (size_t)(n0 + r) * DDIM + (size_t)kc * BK + c * 8;
        cp_async16(stage_base + T_A + soff, g_x + gx);
        cp_async16(stage_base + T_B + soff, g_w + gw);
    }
}

__global__ void __launch_bounds__(GTHREADS, 2)
rank_activation_gemm(const float* __restrict__ av, const float* __restrict__ bv,
                     float* __restrict__ out) {
    extern __shared__ char smem[];
    uint32_t sm = s2u(smem);
    int tid = threadIdx.x;
    int wid = tid >> 5;
    int l = tid & 31;
    int wm = wid >> 2;   // 0..1, 64 rows each
    int wn = wid & 3;    // 0..3, 32 cols each

    // N-major inner order: 4 consecutive CTAs share the same x (A) tile in L2
    int m0 = (int)(blockIdx.x >> 2) * BM;
    int n0 = (int)(blockIdx.x & 3) * BN;

    if (tid < 128) {
        ((float*)smem)[tid]       = av[n0 + tid];
        ((float*)smem)[128 + tid] = bv[n0 + tid];
    }

    // per-lane ldmatrix offsets (within a tile)
    int g = l >> 3;
    uint32_t a_sw[4][2], b_sw[2][2];
#pragma unroll
    for (int mt = 0; mt < 4; mt++) {
        int row = wm * 64 + mt * 16 + ((g & 1) << 3) + (l & 7);
#pragma unroll
        for (int s = 0; s < 2; s++) a_sw[mt][s] = swz(row, s * 2 + (g >> 1));
    }
#pragma unroll
    for (int t = 0; t < 2; t++) {
        int row = wn * 32 + t * 16 + ((g >> 1) << 3) + (l & 7);
#pragma unroll
        for (int s = 0; s < 2; s++) b_sw[t][s] = swz(row, s * 2 + (g & 1));
    }

    float acc[4][4][4];
#pragma unroll
    for (int i = 0; i < 4; i++)
#pragma unroll
        for (int j = 0; j < 4; j++)
#pragma unroll
            for (int k = 0; k < 4; k++) acc[i][j][k] = 0.0f;

    // prologue: stages 0..4
#pragma unroll
    for (int p = 0; p < STAGES - 1; p++) {
        load_stage(sm + SM_STAGE0 + p * STAGE_BYTES, m0, n0, p, tid);
        CP_COMMIT();
    }

    for (int kc = 0; kc < NKC; kc++) {
        CP_WAIT4();
        __syncthreads();

        if (kc + STAGES - 1 < NKC)
            load_stage(sm + SM_STAGE0 + ((kc + STAGES - 1) % STAGES) * STAGE_BYTES,
                       m0, n0, kc + STAGES - 1, tid);
        CP_COMMIT();   // uniform group accounting

        uint32_t st = sm + SM_STAGE0 + (kc % STAGES) * STAGE_BYTES;
#pragma unroll
        for (int s = 0; s < 2; s++) {   // two k16 steps per 32-chunk
            uint32_t A[4][4], B[2][4];
#pragma unroll
            for (int t = 0; t < 2; t++) ldsm4(st + T_B + b_sw[t][s], B[t]);
#pragma unroll
            for (int mt = 0; mt < 4; mt++) ldsm4(st + T_A + a_sw[mt][s], A[mt]);
#pragma unroll
            for (int mt = 0; mt < 4; mt++) {
#pragma unroll
                for (int nt = 0; nt < 4; nt++) {
                    const uint32_t* bf = &B[nt >> 1][(nt & 1) * 2];
                    mma_f16(acc[mt][nt], A[mt], bf);
                }
            }
        }
    }

    // epilogue: out = tanh(a*z + b)
    const float* sA = (const float*)smem;
    const float* sB = (const float*)smem + 128;
#pragma unroll
    for (int mt = 0; mt < 4; mt++) {
        int row = m0 + wm * 64 + mt * 16 + (l >> 2);
#pragma unroll
        for (int nt = 0; nt < 4; nt++) {
            int cl = wn * 32 + nt * 8 + 2 * (l & 3);
            float a0 = sA[cl], a1 = sA[cl + 1];
            float b0 = sB[cl], b1 = sB[cl + 1];
            float2 v0, v1;
            v0.x = tanhf(fmaf(a0, acc[mt][nt][0], b0));
            v0.y = tanhf(fmaf(a1, acc[mt][nt][1], b1));
            v1.x = tanhf(fmaf(a0, acc[mt][nt][2], b0));
            v1.y = tanhf(fmaf(a1, acc[mt][nt][3], b1));
            *reinterpret_cast<float2*>(out + (size_t)row * FDIM + n0 + cl) = v0;
            *reinterpret_cast<float2*>(out + (size_t)(row + 8) * FDIM + n0 + cl) = v1;
        }
    }
}

extern "C" void kernel_launch(void* const* d_in, const int* in_sizes, int n_in,
                              void* d_out, int out_size) {
    const float* x = (const float*)d_in[0];
    const float* W = (const float*)d_in[1];
    const float* a = (const float*)d_in[2];
    const float* b = (const float*)d_in[3];
    float* out = (float*)d_out;

    convert_all<<<CONV_BLOCKS, 256>>>(x, W);

    cudaFuncSetAttribute(rank_activation_gemm,
                         cudaFuncAttributeMaxDynamicSharedMemorySize, SMEM_TOTAL);
    dim3 grid((BROWS / BM) * (FDIM / BN));   // 256 * 4 = 1024
    rank_activation_gemm<<<grid, GTHREADS, SMEM_TOTAL>>>(a, b, out);
}